// round 13
// baseline (speedup 1.0000x reference)
#include <cuda_runtime.h>
#include <mma.h>
#include <cstdint>

using namespace nvcuda;

#define BT   65536
#define T_   2048
#define B_   32
#define H_   768
#define G4   3072

typedef unsigned long long ull;

// ---------------- scratch (static device memory; no allocs) ----------------
__device__ float g_m1[(size_t)BT * 256];
__device__ float g_m2[(size_t)BT * 256];
__device__ float g_xr[(size_t)BT * 512];    // x pre-rounded to tf32
__device__ float g_wr[(size_t)H_ * G4];     // w_ih pre-rounded to tf32
__device__ float g_xg[(size_t)BT * G4];     // [b*T+t][4H]  (NO bias; added in scan)
__device__ float g_hs[(size_t)BT * H_];     // [b*T+t][H]
__device__ float g_h[2][H_ * B_];           // double-buffered h, layout [j][b]
__device__ float g_bias[G4];
__device__ unsigned g_flag[128 * 32];       // per-block flags, 128B stride

// ---------------- helpers ----------------
__device__ __forceinline__ ull pk2(float lo, float hi) {
    ull r; asm("mov.b64 %0,{%1,%2};" : "=l"(r) : "f"(lo), "f"(hi)); return r;
}
__device__ __forceinline__ void fma2(ull& d, ull a, ull b) {
    asm("fma.rn.f32x2 %0,%1,%2,%0;" : "+l"(d) : "l"(a), "l"(b));
}
__device__ __forceinline__ float2 upk2(ull v) {
    float lo, hi; asm("mov.b64 {%0,%1},%2;" : "=f"(lo), "=f"(hi) : "l"(v));
    float2 r; r.x = lo; r.y = hi; return r;
}
__device__ __forceinline__ float sigf(float x) {
    return __fdividef(1.f, 1.f + __expf(-x));
}
__device__ __forceinline__ float tanh_(float x) {
    return 2.f * sigf(2.f * x) - 1.f;
}
__device__ __forceinline__ uint32_t smem_u32(const void* p) {
    uint32_t a;
    asm("{ .reg .u64 t; cvta.to.shared.u64 t, %1; cvt.u32.u64 %0, t; }" : "=r"(a) : "l"(p));
    return a;
}
__device__ __forceinline__ float rtf32(float f) {
    unsigned o; asm("cvt.rna.tf32.f32 %0, %1;" : "=r"(o) : "f"(f));
    return __uint_as_float(o);
}

// ---------------- init: fused bias + flag reset ----------------
__global__ void init_kernel(const float* __restrict__ bi, const float* __restrict__ bh) {
    int i = blockIdx.x * 256 + threadIdx.x;
    if (i < 128 * 32) g_flag[i] = 0u;
    if (i < G4) g_bias[i] = bi[i] + bh[i];
}

// ---------------- tf32 pre-rounding ----------------
__global__ void round_x_kernel(const float* __restrict__ x) {
    size_t i = ((size_t)blockIdx.x * 256 + threadIdx.x) * 4;
    float4 v = *(const float4*)(x + i);
    v.x = rtf32(v.x); v.y = rtf32(v.y); v.z = rtf32(v.z); v.w = rtf32(v.w);
    *(float4*)(g_xr + i) = v;
}
__global__ void round_w_kernel(const float* __restrict__ w) {
    size_t i = ((size_t)blockIdx.x * 256 + threadIdx.x) * 4;
    float4 v = *(const float4*)(w + i);
    v.x = rtf32(v.x); v.y = rtf32(v.y); v.z = rtf32(v.z); v.w = rtf32(v.w);
    *(float4*)(g_wr + i) = v;
}

// ---------------- tf32 WMMA GEMM for xg: 3-stage pipeline, NO bias ----------------
// C[65536,3072] = concat(xr[.,512], m2[.,256]) @ Wr[768,3072]
// One __syncthreads per 32-k chunk; compute overlaps two in-flight loads.
// SMEM 105984 B -> 2 CTAs/SM.
#define XA_LD 36
#define XB_LD 132
#define XS_A  (128 * XA_LD)
#define XS_B  (32 * XB_LD)
#define XS_TOTAL (3 * XS_A + 3 * XS_B)      // 26496 floats = 105984 B

__global__ __launch_bounds__(256, 2)
void xg_wmma_kernel(const float* __restrict__ m2p)
{
    extern __shared__ float xsm[];
    float* As = xsm;
    float* Bs = xsm + 3 * XS_A;

    const int tid = threadIdx.x;
    const int warp = tid >> 5;
    const int bm = blockIdx.y * 128, bn = blockIdx.x * 128;
    const int wm = (warp & 3) * 32;
    const int wn = (warp >> 2) * 64;

    wmma::fragment<wmma::accumulator, 16, 16, 8, float> acc[2][4];
#pragma unroll
    for (int i = 0; i < 2; i++)
#pragma unroll
        for (int j = 0; j < 4; j++) wmma::fill_fragment(acc[i][j], 0.f);

    auto cp_tile = [&](int t, int buf) {
        const int kf = t * 32;
        float* ad = As + buf * XS_A;
#pragma unroll
        for (int i = 0; i < 4; i++) {
            int c = tid + 256 * i;
            int row = c >> 3, kc = (c & 7) * 4;
            int kg = kf + kc;
            const float* src = (kg < 512)
                ? (g_xr + (size_t)(bm + row) * 512 + kg)
                : (m2p  + (size_t)(bm + row) * 256 + (kg - 512));
            uint32_t d = smem_u32(ad + row * XA_LD + kc);
            asm volatile("cp.async.cg.shared.global [%0],[%1],16;" :: "r"(d), "l"(src));
        }
        float* bd = Bs + buf * XS_B;
#pragma unroll
        for (int i = 0; i < 4; i++) {
            int c = tid + 256 * i;
            int kr = c >> 5, nc = (c & 31) * 4;
            const float* src = g_wr + (size_t)(kf + kr) * G4 + bn + nc;
            uint32_t d = smem_u32(bd + kr * XB_LD + nc);
            asm volatile("cp.async.cg.shared.global [%0],[%1],16;" :: "r"(d), "l"(src));
        }
    };

    // prologue: stages 0 and 1 in flight
    cp_tile(0, 0);
    asm volatile("cp.async.commit_group;" ::: "memory");
    cp_tile(1, 1);
    asm volatile("cp.async.commit_group;" ::: "memory");

    for (int t = 0; t < 24; t++) {
        if (t == 23) asm volatile("cp.async.wait_group 0;" ::: "memory");
        else         asm volatile("cp.async.wait_group 1;" ::: "memory");
        __syncthreads();   // tile t visible; all warps done reading buf (t+2)%3

        if (t + 2 < 24) {
            cp_tile(t + 2, (t + 2) % 3);
            asm volatile("cp.async.commit_group;" ::: "memory");
        }

        const float* At = As + (t % 3) * XS_A + wm * XA_LD;
        const float* Bt = Bs + (t % 3) * XS_B + wn;
#pragma unroll
        for (int ks = 0; ks < 4; ks++) {
            wmma::fragment<wmma::matrix_a, 16, 16, 8, wmma::precision::tf32,
                           wmma::row_major> af[2];
            wmma::fragment<wmma::matrix_b, 16, 16, 8, wmma::precision::tf32,
                           wmma::row_major> bf[4];
#pragma unroll
            for (int i = 0; i < 2; i++)
                wmma::load_matrix_sync(af[i], At + i * 16 * XA_LD + ks * 8, XA_LD);
#pragma unroll
            for (int j = 0; j < 4; j++)
                wmma::load_matrix_sync(bf[j], Bt + ks * 8 * XB_LD + j * 16, XB_LD);
#pragma unroll
            for (int i = 0; i < 2; i++)
#pragma unroll
                for (int j = 0; j < 4; j++)
                    wmma::mma_sync(acc[i][j], af[i], bf[j], acc[i][j]);
        }
    }

    const int row0 = bm + wm, col0 = bn + wn;
#pragma unroll
    for (int i = 0; i < 2; i++)
#pragma unroll
        for (int j = 0; j < 4; j++)
            wmma::store_matrix_sync(g_xg + (size_t)(row0 + i * 16) * G4 + col0 + j * 16,
                                    acc[i][j], G4, wmma::mem_row_major);
}

// ---------------- generic fp32 SGEMM (prenet + proj) ----------------
__device__ __forceinline__ int swz(int c) { return c + ((c >> 5) << 2); }

__global__ __launch_bounds__(256, 2)
void sgemm_kernel(const float* __restrict__ A1, int lda1,
                  const float* __restrict__ A2, int lda2, int split,
                  const float* __restrict__ W,
                  const float* __restrict__ bias, int relu, int rnd,
                  float* __restrict__ C, int N, int K)
{
    __shared__ float As[16][132];
    __shared__ float Bs[16][144];
    const int tid = threadIdx.x;
    const int tx = tid & 15, ty = tid >> 4;
    const int bm = blockIdx.y << 7, bn = blockIdx.x << 7;

    ull acc[8][4];
#pragma unroll
    for (int i = 0; i < 8; i++)
#pragma unroll
        for (int j = 0; j < 4; j++) acc[i][j] = 0ull;

    const int aq0 = tid, aq1 = tid + 256;
    const int ar0 = aq0 >> 2, ak0 = (aq0 & 3) << 2;
    const int ar1 = aq1 >> 2, ak1 = (aq1 & 3) << 2;
    const int bkk = tid >> 5, bcc = (tid & 31) << 2;

    float4 pa0, pa1, pb0, pb1;

    auto ldTiles = [&](int k0) {
        int kg0 = k0 + ak0;
        pa0 = (kg0 < split)
            ? *(const float4*)(A1 + (size_t)(bm + ar0) * lda1 + kg0)
            : *(const float4*)(A2 + (size_t)(bm + ar0) * lda2 + (kg0 - split));
        int kg1 = k0 + ak1;
        pa1 = (kg1 < split)
            ? *(const float4*)(A1 + (size_t)(bm + ar1) * lda1 + kg1)
            : *(const float4*)(A2 + (size_t)(bm + ar1) * lda2 + (kg1 - split));
        pb0 = *(const float4*)(W + (size_t)(k0 + bkk) * N + bn + bcc);
        pb1 = *(const float4*)(W + (size_t)(k0 + bkk + 8) * N + bn + bcc);
    };
    auto stTiles = [&]() {
        As[ak0 + 0][ar0] = pa0.x; As[ak0 + 1][ar0] = pa0.y;
        As[ak0 + 2][ar0] = pa0.z; As[ak0 + 3][ar0] = pa0.w;
        As[ak1 + 0][ar1] = pa1.x; As[ak1 + 1][ar1] = pa1.y;
        As[ak1 + 2][ar1] = pa1.z; As[ak1 + 3][ar1] = pa1.w;
        *(float4*)&Bs[bkk][swz(bcc)] = pb0;
        *(float4*)&Bs[bkk + 8][swz(bcc)] = pb1;
    };
    auto comp = [&]() {
#pragma unroll
        for (int kk = 0; kk < 16; kk++) {
            float4 a0 = *(const float4*)&As[kk][ty << 3];
            float4 a1 = *(const float4*)&As[kk][(ty << 3) + 4];
            ulonglong2 b01 = *(const ulonglong2*)&Bs[kk][swz(tx << 3)];
            ulonglong2 b23 = *(const ulonglong2*)&Bs[kk][swz((tx << 3) + 4)];
            float ar[8] = {a0.x, a0.y, a0.z, a0.w, a1.x, a1.y, a1.z, a1.w};
#pragma unroll
            for (int i = 0; i < 8; i++) {
                ull av = pk2(ar[i], ar[i]);
                fma2(acc[i][0], av, b01.x);
                fma2(acc[i][1], av, b01.y);
                fma2(acc[i][2], av, b23.x);
                fma2(acc[i][3], av, b23.y);
            }
        }
    };

    ldTiles(0);
    stTiles();
    __syncthreads();
    for (int k0 = 0; k0 < K; k0 += 16) {
        bool more = (k0 + 16) < K;
        if (more) ldTiles(k0 + 16);
        comp();
        __syncthreads();
        if (more) { stTiles(); __syncthreads(); }
    }

#pragma unroll
    for (int i = 0; i < 8; i++) {
        int row = bm + (ty << 3) + i;
        float* cp = C + (size_t)row * N + bn + (tx << 3);
#pragma unroll
        for (int j = 0; j < 4; j++) {
            float2 v = upk2(acc[i][j]);
            if (bias) {
                int col = bn + (tx << 3) + 2 * j;
                v.x += bias[col]; v.y += bias[col + 1];
            }
            if (relu) { v.x = fmaxf(v.x, 0.f); v.y = fmaxf(v.y, 0.f); }
            if (rnd)  { v.x = rtf32(v.x); v.y = rtf32(v.y); }
            *(float2*)(cp + 2 * j) = v;
        }
    }
}

// ---------------- persistent LSTM scan (fp32, R9 base + bias-in-registers) ----------------
#define RED_W 776
#define SMEM_SCAN_FLOATS (18432 + 16 * RED_W + 768 + 192)

__device__ __forceinline__ void pre_xg(int t, int tid, int j0, float* xgv) {
    if (tid < 192) {
        int u = tid >> 5, b = tid & 31;
        const float* xp = g_xg + (size_t)(b * T_ + t) * G4 + j0 + u;
        xgv[0] = __ldcg(xp);
        xgv[1] = __ldcg(xp + H_);
        xgv[2] = __ldcg(xp + 2 * H_);
        xgv[3] = __ldcg(xp + 3 * H_);
    }
}

__global__ __launch_bounds__(512, 1)
void scan_kernel(const float* __restrict__ w_hh)
{
    extern __shared__ float sm[];
    float* w_s   = sm;                       // 18432
    float* red_f = sm + 18432;               // 16 * RED_W
    float* red2  = red_f + 16 * RED_W;       // 768
    float* c_s   = red2 + 768;               // 192

    const int tid = threadIdx.x, lane = tid & 31, warp = tid >> 5;
    const int j0 = blockIdx.x * 6;

    for (int idx = tid; idx < 768 * 24; idx += 512) {
        int k = idx / 24, c = idx - k * 24;
        int q = c / 6, u = c - q * 6;
        w_s[idx] = w_hh[(size_t)k * G4 + q * H_ + j0 + u];
    }
    // per-thread LSTM bias (b_ih+b_hh), loaded once for all 2048 steps
    float xbias[4] = {0.f, 0.f, 0.f, 0.f};
    if (tid < 192) {
        c_s[tid] = 0.f;
        int u = tid >> 5, b = tid & 31;
        g_h[0][(j0 + u) * 32 + b] = 0.f;
#pragma unroll
        for (int q = 0; q < 4; q++) xbias[q] = g_bias[q * H_ + j0 + u];
    }
    __syncthreads();
    if (tid == 0) {
        __threadfence();
        asm volatile("st.release.gpu.u32 [%0],%1;"
                     :: "l"(&g_flag[blockIdx.x << 5]), "r"(1u) : "memory");
    }

    const unsigned* fp = &g_flag[((warp << 3) + (lane & 7)) << 5];

    float xga[4];
    pre_xg(0, tid, j0, xga);

    for (int t = 0; t < T_; t++) {
        const float* hcur = g_h[t & 1];
        float*       hnxt = g_h[(t + 1) & 1];
        const unsigned target = (unsigned)(t + 1);

        unsigned v;
        do {
            asm volatile("ld.acquire.gpu.u32 %0,[%1];" : "=r"(v) : "l"(fp) : "memory");
        } while (!__all_sync(0xffffffffu, v >= target));

        float xgb[4];
        pre_xg(t + 1 < T_ ? t + 1 : T_ - 1, tid, j0, xgb);

        const float* hp  = hcur + warp * 48 * 32 + lane;
        const float* wsp = w_s + warp * 48 * 24;

        float bufA[12], bufB[12];
#pragma unroll
        for (int i = 0; i < 12; i++) bufA[i] = __ldcg(hp + i * 32);
#pragma unroll
        for (int i = 0; i < 12; i++) bufB[i] = __ldcg(hp + (12 + i) * 32);

        ull acc[12];
#pragma unroll
        for (int j = 0; j < 12; j++) acc[j] = 0ull;

#pragma unroll
        for (int c = 0; c < 4; c++) {
            float* cur = (c & 1) ? bufB : bufA;
#pragma unroll
            for (int i = 0; i < 12; i++) {
                int k = c * 12 + i;
                ull hv = pk2(cur[i], cur[i]);
                const ulonglong2* wv = (const ulonglong2*)(wsp + k * 24);
                ulonglong2 w0 = wv[0], w1 = wv[1], w2 = wv[2];
                ulonglong2 w3 = wv[3], w4 = wv[4], w5 = wv[5];
                fma2(acc[0],  hv, w0.x); fma2(acc[1],  hv, w0.y);
                fma2(acc[2],  hv, w1.x); fma2(acc[3],  hv, w1.y);
                fma2(acc[4],  hv, w2.x); fma2(acc[5],  hv, w2.y);
                fma2(acc[6],  hv, w3.x); fma2(acc[7],  hv, w3.y);
                fma2(acc[8],  hv, w4.x); fma2(acc[9],  hv, w4.y);
                fma2(acc[10], hv, w5.x); fma2(acc[11], hv, w5.y);
            }
            if (c < 2) {
#pragma unroll
                for (int i = 0; i < 12; i++)
                    cur[i] = __ldcg(hp + ((c + 2) * 12 + i) * 32);
            }
        }

        {
            float* rp = red_f + warp * RED_W + 2 * lane;
#pragma unroll
            for (int j = 0; j < 12; j++) {
                float2 v2 = upk2(acc[j]);
                *(float2*)(rp + j * 64) = v2;
            }
        }
        __syncthreads();

        for (int s = tid; s < 768; s += 512) {
            float a0 = 0.f, a1 = 0.f, a2 = 0.f, a3 = 0.f;
#pragma unroll
            for (int w = 0; w < 16; w += 4) {
                a0 += red_f[(w + 0) * RED_W + s];
                a1 += red_f[(w + 1) * RED_W + s];
                a2 += red_f[(w + 2) * RED_W + s];
                a3 += red_f[(w + 3) * RED_W + s];
            }
            red2[s] = (a0 + a1) + (a2 + a3);
        }
        __syncthreads();

        float hn = 0.f;
        if (tid < 192) {
            int u = tid >> 5, b = tid & 31;
            float pre[4];
#pragma unroll
            for (int q = 0; q < 4; q++) {
                int c = q * 6 + u;
                pre[q] = xga[q] + xbias[q] + red2[(c >> 1) * 64 + 2 * b + (c & 1)];
            }
            float ig = sigf(pre[0]);
            float fg = sigf(pre[1]);
            float gg = tanh_(pre[2]);
            float og = sigf(pre[3]);
            float cn = fg * c_s[u * 32 + b] + ig * gg;
            c_s[u * 32 + b] = cn;
            hn = og * tanh_(cn);
            hnxt[(j0 + u) * 32 + b] = hn;
        }
        __syncthreads();
        if (tid == 0) {
            __threadfence();
            asm volatile("st.release.gpu.u32 [%0],%1;"
                         :: "l"(&g_flag[blockIdx.x << 5]), "r"((unsigned)(t + 2)) : "memory");
        }

        if (tid < 192) {
            int u = tid >> 5, b = tid & 31;
            g_hs[(size_t)(b * T_ + t) * H_ + j0 + u] = hn;
        }

        xga[0] = xgb[0]; xga[1] = xgb[1]; xga[2] = xgb[2]; xga[3] = xgb[3];
    }
}

// ---------------- host launcher ----------------
extern "C" void kernel_launch(void* const* d_in, const int* in_sizes, int n_in,
                              void* d_out, int out_size)
{
    const float* x      = (const float*)d_in[0];
    const float* mels   = (const float*)d_in[1];
    const float* w1     = (const float*)d_in[2];
    const float* b1     = (const float*)d_in[3];
    const float* w2     = (const float*)d_in[4];
    const float* b2     = (const float*)d_in[5];
    const float* w_ih   = (const float*)d_in[6];
    const float* w_hh   = (const float*)d_in[7];
    const float* b_ih   = (const float*)d_in[8];
    const float* b_hh   = (const float*)d_in[9];
    const float* w_proj = (const float*)d_in[10];
    float* out = (float*)d_out;

    float *p_m1, *p_m2, *p_hs;
    cudaGetSymbolAddress((void**)&p_m1, g_m1);
    cudaGetSymbolAddress((void**)&p_m2, g_m2);
    cudaGetSymbolAddress((void**)&p_hs, g_hs);

    cudaFuncSetAttribute(scan_kernel, cudaFuncAttributeMaxDynamicSharedMemorySize,
                         SMEM_SCAN_FLOATS * 4);
    cudaFuncSetAttribute(xg_wmma_kernel, cudaFuncAttributeMaxDynamicSharedMemorySize,
                         XS_TOTAL * 4);

    // init + tf32 pre-rounding
    init_kernel<<<16, 256>>>(b_ih, b_hh);
    round_x_kernel<<<BT * 512 / 1024, 256>>>(x);
    round_w_kernel<<<H_ * G4 / 1024, 256>>>(w_ih);

    // PreNet layer 1: [65536,128] @ [128,256] + b1, relu
    sgemm_kernel<<<dim3(2, 512), 256>>>(mels, 128, mels, 128, 128,
                                        w1, b1, 1, 0, p_m1, 256, 128);
    // PreNet layer 2: + b2, relu, output rounded to tf32 (feeds xg tensor GEMM)
    sgemm_kernel<<<dim3(2, 512), 256>>>(p_m1, 256, p_m1, 256, 256,
                                        w2, b2, 1, 1, p_m2, 256, 256);

    // xg = concat(xr, m2) @ wr  — tf32 mma.sync, 3-stage pipeline, 2 CTA/SM
    xg_wmma_kernel<<<dim3(24, 512), 256, XS_TOTAL * 4>>>(p_m2);

    // LSTM recurrence (fp32 persistent scan; bias folded in here)
    scan_kernel<<<128, 512, SMEM_SCAN_FLOATS * 4>>>(w_hh);

    // projection: [65536,768] @ [768,128]
    sgemm_kernel<<<dim3(1, 512), 256>>>(p_hs, 768, p_hs, 768, 768,
                                        w_proj, nullptr, 0, 0, out, 128, 768);
}

// round 15
// speedup vs baseline: 1.0583x; 1.0583x over previous
#include <cuda_runtime.h>
#include <mma.h>
#include <cstdint>

using namespace nvcuda;

#define BT   65536
#define T_   2048
#define B_   32
#define H_   768
#define G4   3072

typedef unsigned long long ull;

// ---------------- scratch (static device memory; no allocs) ----------------
__device__ float g_m1[(size_t)BT * 256];
__device__ float g_m2[(size_t)BT * 256];
__device__ float g_xr[(size_t)BT * 512];    // x pre-rounded to tf32
__device__ float g_wr[(size_t)H_ * G4];     // w_ih pre-rounded to tf32
__device__ float g_wpr[(size_t)H_ * 128];   // w_proj pre-rounded to tf32
__device__ float g_xg[(size_t)BT * G4];     // [b*T+t][4H]
__device__ float g_hs[(size_t)BT * H_];     // [b*T+t][H], tf32-rounded (proj input)
__device__ float g_h[2][H_ * B_];           // double-buffered h, layout [j][b]
__device__ float g_bias[G4];
__device__ unsigned g_flag[128 * 32];       // per-block flags, 128B stride

// ---------------- helpers ----------------
__device__ __forceinline__ ull pk2(float lo, float hi) {
    ull r; asm("mov.b64 %0,{%1,%2};" : "=l"(r) : "f"(lo), "f"(hi)); return r;
}
__device__ __forceinline__ void fma2(ull& d, ull a, ull b) {
    asm("fma.rn.f32x2 %0,%1,%2,%0;" : "+l"(d) : "l"(a), "l"(b));
}
__device__ __forceinline__ float2 upk2(ull v) {
    float lo, hi; asm("mov.b64 {%0,%1},%2;" : "=f"(lo), "=f"(hi) : "l"(v));
    float2 r; r.x = lo; r.y = hi; return r;
}
__device__ __forceinline__ float sigf(float x) {
    return __fdividef(1.f, 1.f + __expf(-x));
}
__device__ __forceinline__ float tanh_(float x) {
    return 2.f * sigf(2.f * x) - 1.f;
}
__device__ __forceinline__ uint32_t smem_u32(const void* p) {
    uint32_t a;
    asm("{ .reg .u64 t; cvta.to.shared.u64 t, %1; cvt.u32.u64 %0, t; }" : "=r"(a) : "l"(p));
    return a;
}
__device__ __forceinline__ float rtf32(float f) {
    unsigned o; asm("cvt.rna.tf32.f32 %0, %1;" : "=r"(o) : "f"(f));
    return __uint_as_float(o);
}

// ---------------- init: fused bias + flag reset ----------------
__global__ void init_kernel(const float* __restrict__ bi, const float* __restrict__ bh) {
    int i = blockIdx.x * 256 + threadIdx.x;
    if (i < 128 * 32) g_flag[i] = 0u;
    if (i < G4) g_bias[i] = bi[i] + bh[i];
}

// ---------------- tf32 pre-rounding ----------------
__global__ void round_x_kernel(const float* __restrict__ x) {
    size_t i = ((size_t)blockIdx.x * 256 + threadIdx.x) * 4;
    float4 v = *(const float4*)(x + i);
    v.x = rtf32(v.x); v.y = rtf32(v.y); v.z = rtf32(v.z); v.w = rtf32(v.w);
    *(float4*)(g_xr + i) = v;
}
__global__ void round_w_kernel(const float* __restrict__ w) {
    size_t i = ((size_t)blockIdx.x * 256 + threadIdx.x) * 4;
    float4 v = *(const float4*)(w + i);
    v.x = rtf32(v.x); v.y = rtf32(v.y); v.z = rtf32(v.z); v.w = rtf32(v.w);
    *(float4*)(g_wr + i) = v;
}
__global__ void round_wp_kernel(const float* __restrict__ w) {
    size_t i = ((size_t)blockIdx.x * 256 + threadIdx.x) * 4;
    float4 v = *(const float4*)(w + i);
    v.x = rtf32(v.x); v.y = rtf32(v.y); v.z = rtf32(v.z); v.w = rtf32(v.w);
    *(float4*)(g_wpr + i) = v;
}

// ---------------- tf32 WMMA GEMM for xg (R9 exact: 2-stage, bias epilogue) ----------------
#define XA_LD 36
#define XB_LD 132
#define XS_A  (128 * XA_LD)
#define XS_B  (32 * XB_LD)
#define XS_BIAS_OFF (2 * XS_A + 2 * XS_B)
#define XS_TOTAL (XS_BIAS_OFF + 16 * 128)   // floats

__global__ __launch_bounds__(256, 2)
void xg_wmma_kernel(const float* __restrict__ m2p)
{
    extern __shared__ float xsm[];
    float* As     = xsm;
    float* Bs     = xsm + 2 * XS_A;
    float* bias_s = xsm + XS_BIAS_OFF;

    const int tid = threadIdx.x;
    const int warp = tid >> 5;
    const int bm = blockIdx.y * 128, bn = blockIdx.x * 128;
    const int wm = (warp & 3) * 32;
    const int wn = (warp >> 2) * 64;

    for (int i = tid; i < 16 * 128; i += 256)
        bias_s[i] = g_bias[bn + (i & 127)];

    wmma::fragment<wmma::accumulator, 16, 16, 8, float> acc[2][4];
#pragma unroll
    for (int i = 0; i < 2; i++)
#pragma unroll
        for (int j = 0; j < 4; j++) wmma::fill_fragment(acc[i][j], 0.f);

    auto cp_tile = [&](int t, int buf) {
        const int kf = t * 32;
        float* ad = As + buf * XS_A;
#pragma unroll
        for (int i = 0; i < 4; i++) {
            int c = tid + 256 * i;
            int row = c >> 3, kc = (c & 7) * 4;
            int kg = kf + kc;
            const float* src = (kg < 512)
                ? (g_xr + (size_t)(bm + row) * 512 + kg)
                : (m2p  + (size_t)(bm + row) * 256 + (kg - 512));
            uint32_t d = smem_u32(ad + row * XA_LD + kc);
            asm volatile("cp.async.cg.shared.global [%0],[%1],16;" :: "r"(d), "l"(src));
        }
        float* bd = Bs + buf * XS_B;
#pragma unroll
        for (int i = 0; i < 4; i++) {
            int c = tid + 256 * i;
            int kr = c >> 5, nc = (c & 31) * 4;
            const float* src = g_wr + (size_t)(kf + kr) * G4 + bn + nc;
            uint32_t d = smem_u32(bd + kr * XB_LD + nc);
            asm volatile("cp.async.cg.shared.global [%0],[%1],16;" :: "r"(d), "l"(src));
        }
    };

    cp_tile(0, 0);
    asm volatile("cp.async.commit_group;" ::: "memory");

    for (int t = 0; t < 24; t++) {
        if (t + 1 < 24) {
            cp_tile(t + 1, (t + 1) & 1);
            asm volatile("cp.async.commit_group;" ::: "memory");
            asm volatile("cp.async.wait_group 1;" ::: "memory");
        } else {
            asm volatile("cp.async.wait_group 0;" ::: "memory");
        }
        __syncthreads();

        const float* At = As + (t & 1) * XS_A + wm * XA_LD;
        const float* Bt = Bs + (t & 1) * XS_B + wn;
#pragma unroll
        for (int ks = 0; ks < 4; ks++) {
            wmma::fragment<wmma::matrix_a, 16, 16, 8, wmma::precision::tf32,
                           wmma::row_major> af[2];
            wmma::fragment<wmma::matrix_b, 16, 16, 8, wmma::precision::tf32,
                           wmma::row_major> bf[4];
#pragma unroll
            for (int i = 0; i < 2; i++)
                wmma::load_matrix_sync(af[i], At + i * 16 * XA_LD + ks * 8, XA_LD);
#pragma unroll
            for (int j = 0; j < 4; j++)
                wmma::load_matrix_sync(bf[j], Bt + ks * 8 * XB_LD + j * 16, XB_LD);
#pragma unroll
            for (int i = 0; i < 2; i++)
#pragma unroll
                for (int j = 0; j < 4; j++)
                    wmma::mma_sync(acc[i][j], af[i], bf[j], acc[i][j]);
        }
        __syncthreads();
    }

    const int row0 = bm + wm, col0 = bn + wn;
#pragma unroll
    for (int i = 0; i < 2; i++)
#pragma unroll
        for (int j = 0; j < 4; j++) {
            wmma::fragment<wmma::accumulator, 16, 16, 8, float> bfr;
            wmma::load_matrix_sync(bfr, bias_s + wn + j * 16, 128, wmma::mem_row_major);
#pragma unroll
            for (int e = 0; e < bfr.num_elements; e++)
                acc[i][j].x[e] += bfr.x[e];
            wmma::store_matrix_sync(g_xg + (size_t)(row0 + i * 16) * G4 + col0 + j * 16,
                                    acc[i][j], G4, wmma::mem_row_major);
        }
}

// ---------------- tf32 WMMA GEMM for proj: out = hs_r @ wpr ----------------
// [65536,768] @ [768,128], same 2-stage structure as xg, no bias.
#define PS_TOTAL (2 * XS_A + 2 * XS_B)      // 17664 floats = 70656 B

__global__ __launch_bounds__(256, 2)
void proj_wmma_kernel(float* __restrict__ out)
{
    extern __shared__ float psm[];
    float* As = psm;
    float* Bs = psm + 2 * XS_A;

    const int tid = threadIdx.x;
    const int warp = tid >> 5;
    const int bm = blockIdx.x * 128;
    const int wm = (warp & 3) * 32;
    const int wn = (warp >> 2) * 64;

    wmma::fragment<wmma::accumulator, 16, 16, 8, float> acc[2][4];
#pragma unroll
    for (int i = 0; i < 2; i++)
#pragma unroll
        for (int j = 0; j < 4; j++) wmma::fill_fragment(acc[i][j], 0.f);

    auto cp_tile = [&](int t, int buf) {
        const int kf = t * 32;
        float* ad = As + buf * XS_A;
#pragma unroll
        for (int i = 0; i < 4; i++) {
            int c = tid + 256 * i;
            int row = c >> 3, kc = (c & 7) * 4;
            const float* src = g_hs + (size_t)(bm + row) * H_ + kf + kc;
            uint32_t d = smem_u32(ad + row * XA_LD + kc);
            asm volatile("cp.async.cg.shared.global [%0],[%1],16;" :: "r"(d), "l"(src));
        }
        float* bd = Bs + buf * XS_B;
#pragma unroll
        for (int i = 0; i < 4; i++) {
            int c = tid + 256 * i;
            int kr = c >> 5, nc = (c & 31) * 4;
            const float* src = g_wpr + (size_t)(kf + kr) * 128 + nc;
            uint32_t d = smem_u32(bd + kr * XB_LD + nc);
            asm volatile("cp.async.cg.shared.global [%0],[%1],16;" :: "r"(d), "l"(src));
        }
    };

    cp_tile(0, 0);
    asm volatile("cp.async.commit_group;" ::: "memory");

    for (int t = 0; t < 24; t++) {
        if (t + 1 < 24) {
            cp_tile(t + 1, (t + 1) & 1);
            asm volatile("cp.async.commit_group;" ::: "memory");
            asm volatile("cp.async.wait_group 1;" ::: "memory");
        } else {
            asm volatile("cp.async.wait_group 0;" ::: "memory");
        }
        __syncthreads();

        const float* At = As + (t & 1) * XS_A + wm * XA_LD;
        const float* Bt = Bs + (t & 1) * XS_B + wn;
#pragma unroll
        for (int ks = 0; ks < 4; ks++) {
            wmma::fragment<wmma::matrix_a, 16, 16, 8, wmma::precision::tf32,
                           wmma::row_major> af[2];
            wmma::fragment<wmma::matrix_b, 16, 16, 8, wmma::precision::tf32,
                           wmma::row_major> bf[4];
#pragma unroll
            for (int i = 0; i < 2; i++)
                wmma::load_matrix_sync(af[i], At + i * 16 * XA_LD + ks * 8, XA_LD);
#pragma unroll
            for (int j = 0; j < 4; j++)
                wmma::load_matrix_sync(bf[j], Bt + ks * 8 * XB_LD + j * 16, XB_LD);
#pragma unroll
            for (int i = 0; i < 2; i++)
#pragma unroll
                for (int j = 0; j < 4; j++)
                    wmma::mma_sync(acc[i][j], af[i], bf[j], acc[i][j]);
        }
        __syncthreads();
    }

    const int row0 = bm + wm, col0 = wn;
#pragma unroll
    for (int i = 0; i < 2; i++)
#pragma unroll
        for (int j = 0; j < 4; j++)
            wmma::store_matrix_sync(out + (size_t)(row0 + i * 16) * 128 + col0 + j * 16,
                                    acc[i][j], 128, wmma::mem_row_major);
}

// ---------------- generic fp32 SGEMM (prenet) ----------------
__device__ __forceinline__ int swz(int c) { return c + ((c >> 5) << 2); }

__global__ __launch_bounds__(256, 2)
void sgemm_kernel(const float* __restrict__ A1, int lda1,
                  const float* __restrict__ A2, int lda2, int split,
                  const float* __restrict__ W,
                  const float* __restrict__ bias, int relu, int rnd,
                  float* __restrict__ C, int N, int K)
{
    __shared__ float As[16][132];
    __shared__ float Bs[16][144];
    const int tid = threadIdx.x;
    const int tx = tid & 15, ty = tid >> 4;
    const int bm = blockIdx.y << 7, bn = blockIdx.x << 7;

    ull acc[8][4];
#pragma unroll
    for (int i = 0; i < 8; i++)
#pragma unroll
        for (int j = 0; j < 4; j++) acc[i][j] = 0ull;

    const int aq0 = tid, aq1 = tid + 256;
    const int ar0 = aq0 >> 2, ak0 = (aq0 & 3) << 2;
    const int ar1 = aq1 >> 2, ak1 = (aq1 & 3) << 2;
    const int bkk = tid >> 5, bcc = (tid & 31) << 2;

    float4 pa0, pa1, pb0, pb1;

    auto ldTiles = [&](int k0) {
        int kg0 = k0 + ak0;
        pa0 = (kg0 < split)
            ? *(const float4*)(A1 + (size_t)(bm + ar0) * lda1 + kg0)
            : *(const float4*)(A2 + (size_t)(bm + ar0) * lda2 + (kg0 - split));
        int kg1 = k0 + ak1;
        pa1 = (kg1 < split)
            ? *(const float4*)(A1 + (size_t)(bm + ar1) * lda1 + kg1)
            : *(const float4*)(A2 + (size_t)(bm + ar1) * lda2 + (kg1 - split));
        pb0 = *(const float4*)(W + (size_t)(k0 + bkk) * N + bn + bcc);
        pb1 = *(const float4*)(W + (size_t)(k0 + bkk + 8) * N + bn + bcc);
    };
    auto stTiles = [&]() {
        As[ak0 + 0][ar0] = pa0.x; As[ak0 + 1][ar0] = pa0.y;
        As[ak0 + 2][ar0] = pa0.z; As[ak0 + 3][ar0] = pa0.w;
        As[ak1 + 0][ar1] = pa1.x; As[ak1 + 1][ar1] = pa1.y;
        As[ak1 + 2][ar1] = pa1.z; As[ak1 + 3][ar1] = pa1.w;
        *(float4*)&Bs[bkk][swz(bcc)] = pb0;
        *(float4*)&Bs[bkk + 8][swz(bcc)] = pb1;
    };
    auto comp = [&]() {
#pragma unroll
        for (int kk = 0; kk < 16; kk++) {
            float4 a0 = *(const float4*)&As[kk][ty << 3];
            float4 a1 = *(const float4*)&As[kk][(ty << 3) + 4];
            ulonglong2 b01 = *(const ulonglong2*)&Bs[kk][swz(tx << 3)];
            ulonglong2 b23 = *(const ulonglong2*)&Bs[kk][swz((tx << 3) + 4)];
            float ar[8] = {a0.x, a0.y, a0.z, a0.w, a1.x, a1.y, a1.z, a1.w};
#pragma unroll
            for (int i = 0; i < 8; i++) {
                ull av = pk2(ar[i], ar[i]);
                fma2(acc[i][0], av, b01.x);
                fma2(acc[i][1], av, b01.y);
                fma2(acc[i][2], av, b23.x);
                fma2(acc[i][3], av, b23.y);
            }
        }
    };

    ldTiles(0);
    stTiles();
    __syncthreads();
    for (int k0 = 0; k0 < K; k0 += 16) {
        bool more = (k0 + 16) < K;
        if (more) ldTiles(k0 + 16);
        comp();
        __syncthreads();
        if (more) { stTiles(); __syncthreads(); }
    }

#pragma unroll
    for (int i = 0; i < 8; i++) {
        int row = bm + (ty << 3) + i;
        float* cp = C + (size_t)row * N + bn + (tx << 3);
#pragma unroll
        for (int j = 0; j < 4; j++) {
            float2 v = upk2(acc[i][j]);
            if (bias) {
                int col = bn + (tx << 3) + 2 * j;
                v.x += bias[col]; v.y += bias[col + 1];
            }
            if (relu) { v.x = fmaxf(v.x, 0.f); v.y = fmaxf(v.y, 0.f); }
            if (rnd)  { v.x = rtf32(v.x); v.y = rtf32(v.y); }
            *(float2*)(cp + 2 * j) = v;
        }
    }
}

// ---------------- persistent LSTM scan (fp32, R9 exact; hs stored tf32) ----------------
#define RED_W 776
#define SMEM_SCAN_FLOATS (18432 + 16 * RED_W + 768 + 192)

__device__ __forceinline__ void pre_xg(int t, int tid, int j0, float* xgv) {
    if (tid < 192) {
        int u = tid >> 5, b = tid & 31;
        const float* xp = g_xg + (size_t)(b * T_ + t) * G4 + j0 + u;
        xgv[0] = __ldcg(xp);
        xgv[1] = __ldcg(xp + H_);
        xgv[2] = __ldcg(xp + 2 * H_);
        xgv[3] = __ldcg(xp + 3 * H_);
    }
}

__global__ __launch_bounds__(512, 1)
void scan_kernel(const float* __restrict__ w_hh)
{
    extern __shared__ float sm[];
    float* w_s   = sm;                       // 18432
    float* red_f = sm + 18432;               // 16 * RED_W
    float* red2  = red_f + 16 * RED_W;       // 768
    float* c_s   = red2 + 768;               // 192

    const int tid = threadIdx.x, lane = tid & 31, warp = tid >> 5;
    const int j0 = blockIdx.x * 6;

    for (int idx = tid; idx < 768 * 24; idx += 512) {
        int k = idx / 24, c = idx - k * 24;
        int q = c / 6, u = c - q * 6;
        w_s[idx] = w_hh[(size_t)k * G4 + q * H_ + j0 + u];
    }
    if (tid < 192) {
        c_s[tid] = 0.f;
        int u = tid >> 5, b = tid & 31;
        g_h[0][(j0 + u) * 32 + b] = 0.f;
    }
    __syncthreads();
    if (tid == 0) {
        __threadfence();
        asm volatile("st.release.gpu.u32 [%0],%1;"
                     :: "l"(&g_flag[blockIdx.x << 5]), "r"(1u) : "memory");
    }

    const unsigned* fp = &g_flag[((warp << 3) + (lane & 7)) << 5];

    float xga[4];
    pre_xg(0, tid, j0, xga);

    for (int t = 0; t < T_; t++) {
        const float* hcur = g_h[t & 1];
        float*       hnxt = g_h[(t + 1) & 1];
        const unsigned target = (unsigned)(t + 1);

        unsigned v;
        do {
            asm volatile("ld.acquire.gpu.u32 %0,[%1];" : "=r"(v) : "l"(fp) : "memory");
        } while (!__all_sync(0xffffffffu, v >= target));

        float xgb[4];
        pre_xg(t + 1 < T_ ? t + 1 : T_ - 1, tid, j0, xgb);

        const float* hp  = hcur + warp * 48 * 32 + lane;
        const float* wsp = w_s + warp * 48 * 24;

        float bufA[12], bufB[12];
#pragma unroll
        for (int i = 0; i < 12; i++) bufA[i] = __ldcg(hp + i * 32);
#pragma unroll
        for (int i = 0; i < 12; i++) bufB[i] = __ldcg(hp + (12 + i) * 32);

        ull acc[12];
#pragma unroll
        for (int j = 0; j < 12; j++) acc[j] = 0ull;

#pragma unroll
        for (int c = 0; c < 4; c++) {
            float* cur = (c & 1) ? bufB : bufA;
#pragma unroll
            for (int i = 0; i < 12; i++) {
                int k = c * 12 + i;
                ull hv = pk2(cur[i], cur[i]);
                const ulonglong2* wv = (const ulonglong2*)(wsp + k * 24);
                ulonglong2 w0 = wv[0], w1 = wv[1], w2 = wv[2];
                ulonglong2 w3 = wv[3], w4 = wv[4], w5 = wv[5];
                fma2(acc[0],  hv, w0.x); fma2(acc[1],  hv, w0.y);
                fma2(acc[2],  hv, w1.x); fma2(acc[3],  hv, w1.y);
                fma2(acc[4],  hv, w2.x); fma2(acc[5],  hv, w2.y);
                fma2(acc[6],  hv, w3.x); fma2(acc[7],  hv, w3.y);
                fma2(acc[8],  hv, w4.x); fma2(acc[9],  hv, w4.y);
                fma2(acc[10], hv, w5.x); fma2(acc[11], hv, w5.y);
            }
            if (c < 2) {
#pragma unroll
                for (int i = 0; i < 12; i++)
                    cur[i] = __ldcg(hp + ((c + 2) * 12 + i) * 32);
            }
        }

        {
            float* rp = red_f + warp * RED_W + 2 * lane;
#pragma unroll
            for (int j = 0; j < 12; j++) {
                float2 v2 = upk2(acc[j]);
                *(float2*)(rp + j * 64) = v2;
            }
        }
        __syncthreads();

        for (int s = tid; s < 768; s += 512) {
            float a0 = 0.f, a1 = 0.f, a2 = 0.f, a3 = 0.f;
#pragma unroll
            for (int w = 0; w < 16; w += 4) {
                a0 += red_f[(w + 0) * RED_W + s];
                a1 += red_f[(w + 1) * RED_W + s];
                a2 += red_f[(w + 2) * RED_W + s];
                a3 += red_f[(w + 3) * RED_W + s];
            }
            red2[s] = (a0 + a1) + (a2 + a3);
        }
        __syncthreads();

        float hn = 0.f;
        if (tid < 192) {
            int u = tid >> 5, b = tid & 31;
            float pre[4];
#pragma unroll
            for (int q = 0; q < 4; q++) {
                int c = q * 6 + u;
                pre[q] = xga[q] + red2[(c >> 1) * 64 + 2 * b + (c & 1)];
            }
            float ig = sigf(pre[0]);
            float fg = sigf(pre[1]);
            float gg = tanh_(pre[2]);
            float og = sigf(pre[3]);
            float cn = fg * c_s[u * 32 + b] + ig * gg;
            c_s[u * 32 + b] = cn;
            hn = og * tanh_(cn);
            hnxt[(j0 + u) * 32 + b] = hn;
        }
        __syncthreads();
        if (tid == 0) {
            __threadfence();
            asm volatile("st.release.gpu.u32 [%0],%1;"
                         :: "l"(&g_flag[blockIdx.x << 5]), "r"((unsigned)(t + 2)) : "memory");
        }

        // off-critical-path: tf32-rounded h for the WMMA projection
        if (tid < 192) {
            int u = tid >> 5, b = tid & 31;
            g_hs[(size_t)(b * T_ + t) * H_ + j0 + u] = rtf32(hn);
        }

        xga[0] = xgb[0]; xga[1] = xgb[1]; xga[2] = xgb[2]; xga[3] = xgb[3];
    }
}

// ---------------- host launcher ----------------
extern "C" void kernel_launch(void* const* d_in, const int* in_sizes, int n_in,
                              void* d_out, int out_size)
{
    const float* x      = (const float*)d_in[0];
    const float* mels   = (const float*)d_in[1];
    const float* w1     = (const float*)d_in[2];
    const float* b1     = (const float*)d_in[3];
    const float* w2     = (const float*)d_in[4];
    const float* b2     = (const float*)d_in[5];
    const float* w_ih   = (const float*)d_in[6];
    const float* w_hh   = (const float*)d_in[7];
    const float* b_ih   = (const float*)d_in[8];
    const float* b_hh   = (const float*)d_in[9];
    const float* w_proj = (const float*)d_in[10];
    float* out = (float*)d_out;

    float *p_m1, *p_m2;
    cudaGetSymbolAddress((void**)&p_m1, g_m1);
    cudaGetSymbolAddress((void**)&p_m2, g_m2);

    cudaFuncSetAttribute(scan_kernel, cudaFuncAttributeMaxDynamicSharedMemorySize,
                         SMEM_SCAN_FLOATS * 4);
    cudaFuncSetAttribute(xg_wmma_kernel, cudaFuncAttributeMaxDynamicSharedMemorySize,
                         XS_TOTAL * 4);
    cudaFuncSetAttribute(proj_wmma_kernel, cudaFuncAttributeMaxDynamicSharedMemorySize,
                         PS_TOTAL * 4);

    // init + tf32 pre-rounding
    init_kernel<<<16, 256>>>(b_ih, b_hh);
    round_x_kernel<<<BT * 512 / 1024, 256>>>(x);
    round_w_kernel<<<H_ * G4 / 1024, 256>>>(w_ih);
    round_wp_kernel<<<H_ * 128 / 1024, 256>>>(w_proj);

    // PreNet layer 1: [65536,128] @ [128,256] + b1, relu
    sgemm_kernel<<<dim3(2, 512), 256>>>(mels, 128, mels, 128, 128,
                                        w1, b1, 1, 0, p_m1, 256, 128);
    // PreNet layer 2: + b2, relu, output rounded to tf32 (feeds xg tensor GEMM)
    sgemm_kernel<<<dim3(2, 512), 256>>>(p_m1, 256, p_m1, 256, 256,
                                        w2, b2, 1, 1, p_m2, 256, 256);

    // xg = concat(xr, m2) @ wr + bias  — tf32 mma.sync (R9 exact)
    xg_wmma_kernel<<<dim3(24, 512), 256, XS_TOTAL * 4>>>(p_m2);

    // LSTM recurrence (fp32 persistent scan, R9 exact)
    scan_kernel<<<128, 512, SMEM_SCAN_FLOATS * 4>>>(w_hh);

    // projection: [65536,768] @ [768,128] — tf32 WMMA
    proj_wmma_kernel<<<512, 256, PS_TOTAL * 4>>>(out);
}

// round 16
// speedup vs baseline: 1.1167x; 1.0552x over previous
#include <cuda_runtime.h>
#include <mma.h>
#include <cstdint>

using namespace nvcuda;

#define BT   65536
#define T_   2048
#define B_   32
#define H_   768
#define G4   3072

typedef unsigned long long ull;

// ---------------- scratch (static device memory; no allocs) ----------------
__device__ float g_m1[(size_t)BT * 256];
__device__ float g_m2[(size_t)BT * 256];
__device__ float g_xr[(size_t)BT * 512];    // x pre-rounded to tf32
__device__ float g_wr[(size_t)H_ * G4];     // w_ih pre-rounded to tf32
__device__ float g_xg[(size_t)BT * G4];     // [b*T+t][4H]
__device__ float g_hs[(size_t)BT * H_];     // [b*T+t][H] fp32 (proj input)
__device__ float g_h[2][H_ * B_];           // double-buffered h, [j][b], tf32-rounded
__device__ float g_bias[G4];
__device__ unsigned g_flag[128 * 32];       // per-block flags, 128B stride

// ---------------- helpers ----------------
__device__ __forceinline__ ull pk2(float lo, float hi) {
    ull r; asm("mov.b64 %0,{%1,%2};" : "=l"(r) : "f"(lo), "f"(hi)); return r;
}
__device__ __forceinline__ void fma2(ull& d, ull a, ull b) {
    asm("fma.rn.f32x2 %0,%1,%2,%0;" : "+l"(d) : "l"(a), "l"(b));
}
__device__ __forceinline__ float2 upk2(ull v) {
    float lo, hi; asm("mov.b64 {%0,%1},%2;" : "=f"(lo), "=f"(hi) : "l"(v));
    float2 r; r.x = lo; r.y = hi; return r;
}
__device__ __forceinline__ float sigf(float x) {
    return __fdividef(1.f, 1.f + __expf(-x));
}
__device__ __forceinline__ float tanh_(float x) {
    return 2.f * sigf(2.f * x) - 1.f;
}
__device__ __forceinline__ uint32_t smem_u32(const void* p) {
    uint32_t a;
    asm("{ .reg .u64 t; cvta.to.shared.u64 t, %1; cvt.u32.u64 %0, t; }" : "=r"(a) : "l"(p));
    return a;
}
__device__ __forceinline__ float rtf32(float f) {
    unsigned o; asm("cvt.rna.tf32.f32 %0, %1;" : "=r"(o) : "f"(f));
    return __uint_as_float(o);
}

// m16n8k8 tf32 MMA: D = A@B + D (A row-major, B col-major fragments)
__device__ __forceinline__ void mma8(float& c0, float& c1, float& c2, float& c3,
                                     unsigned a0, unsigned a1, unsigned a2, unsigned a3,
                                     unsigned b0, unsigned b1) {
    asm("mma.sync.aligned.m16n8k8.row.col.f32.tf32.tf32.f32 "
        "{%0,%1,%2,%3},{%4,%5,%6,%7},{%8,%9},{%0,%1,%2,%3};"
        : "+f"(c0), "+f"(c1), "+f"(c2), "+f"(c3)
        : "r"(a0), "r"(a1), "r"(a2), "r"(a3), "r"(b0), "r"(b1));
}

// ---------------- init: fused bias + flag reset ----------------
__global__ void init_kernel(const float* __restrict__ bi, const float* __restrict__ bh) {
    int i = blockIdx.x * 256 + threadIdx.x;
    if (i < 128 * 32) g_flag[i] = 0u;
    if (i < G4) g_bias[i] = bi[i] + bh[i];
}

// ---------------- tf32 pre-rounding ----------------
__global__ void round_x_kernel(const float* __restrict__ x) {
    size_t i = ((size_t)blockIdx.x * 256 + threadIdx.x) * 4;
    float4 v = *(const float4*)(x + i);
    v.x = rtf32(v.x); v.y = rtf32(v.y); v.z = rtf32(v.z); v.w = rtf32(v.w);
    *(float4*)(g_xr + i) = v;
}
__global__ void round_w_kernel(const float* __restrict__ w) {
    size_t i = ((size_t)blockIdx.x * 256 + threadIdx.x) * 4;
    float4 v = *(const float4*)(w + i);
    v.x = rtf32(v.x); v.y = rtf32(v.y); v.z = rtf32(v.z); v.w = rtf32(v.w);
    *(float4*)(g_wr + i) = v;
}

// ---------------- tf32 WMMA GEMM for xg (R9 exact) ----------------
#define XA_LD 36
#define XB_LD 132
#define XS_A  (128 * XA_LD)
#define XS_B  (32 * XB_LD)
#define XS_BIAS_OFF (2 * XS_A + 2 * XS_B)
#define XS_TOTAL (XS_BIAS_OFF + 16 * 128)   // floats

__global__ __launch_bounds__(256, 2)
void xg_wmma_kernel(const float* __restrict__ m2p)
{
    extern __shared__ float xsm[];
    float* As     = xsm;
    float* Bs     = xsm + 2 * XS_A;
    float* bias_s = xsm + XS_BIAS_OFF;

    const int tid = threadIdx.x;
    const int warp = tid >> 5;
    const int bm = blockIdx.y * 128, bn = blockIdx.x * 128;
    const int wm = (warp & 3) * 32;
    const int wn = (warp >> 2) * 64;

    for (int i = tid; i < 16 * 128; i += 256)
        bias_s[i] = g_bias[bn + (i & 127)];

    wmma::fragment<wmma::accumulator, 16, 16, 8, float> acc[2][4];
#pragma unroll
    for (int i = 0; i < 2; i++)
#pragma unroll
        for (int j = 0; j < 4; j++) wmma::fill_fragment(acc[i][j], 0.f);

    auto cp_tile = [&](int t, int buf) {
        const int kf = t * 32;
        float* ad = As + buf * XS_A;
#pragma unroll
        for (int i = 0; i < 4; i++) {
            int c = tid + 256 * i;
            int row = c >> 3, kc = (c & 7) * 4;
            int kg = kf + kc;
            const float* src = (kg < 512)
                ? (g_xr + (size_t)(bm + row) * 512 + kg)
                : (m2p  + (size_t)(bm + row) * 256 + (kg - 512));
            uint32_t d = smem_u32(ad + row * XA_LD + kc);
            asm volatile("cp.async.cg.shared.global [%0],[%1],16;" :: "r"(d), "l"(src));
        }
        float* bd = Bs + buf * XS_B;
#pragma unroll
        for (int i = 0; i < 4; i++) {
            int c = tid + 256 * i;
            int kr = c >> 5, nc = (c & 31) * 4;
            const float* src = g_wr + (size_t)(kf + kr) * G4 + bn + nc;
            uint32_t d = smem_u32(bd + kr * XB_LD + nc);
            asm volatile("cp.async.cg.shared.global [%0],[%1],16;" :: "r"(d), "l"(src));
        }
    };

    cp_tile(0, 0);
    asm volatile("cp.async.commit_group;" ::: "memory");

    for (int t = 0; t < 24; t++) {
        if (t + 1 < 24) {
            cp_tile(t + 1, (t + 1) & 1);
            asm volatile("cp.async.commit_group;" ::: "memory");
            asm volatile("cp.async.wait_group 1;" ::: "memory");
        } else {
            asm volatile("cp.async.wait_group 0;" ::: "memory");
        }
        __syncthreads();

        const float* At = As + (t & 1) * XS_A + wm * XA_LD;
        const float* Bt = Bs + (t & 1) * XS_B + wn;
#pragma unroll
        for (int ks = 0; ks < 4; ks++) {
            wmma::fragment<wmma::matrix_a, 16, 16, 8, wmma::precision::tf32,
                           wmma::row_major> af[2];
            wmma::fragment<wmma::matrix_b, 16, 16, 8, wmma::precision::tf32,
                           wmma::row_major> bf[4];
#pragma unroll
            for (int i = 0; i < 2; i++)
                wmma::load_matrix_sync(af[i], At + i * 16 * XA_LD + ks * 8, XA_LD);
#pragma unroll
            for (int j = 0; j < 4; j++)
                wmma::load_matrix_sync(bf[j], Bt + ks * 8 * XB_LD + j * 16, XB_LD);
#pragma unroll
            for (int i = 0; i < 2; i++)
#pragma unroll
                for (int j = 0; j < 4; j++)
                    wmma::mma_sync(acc[i][j], af[i], bf[j], acc[i][j]);
        }
        __syncthreads();
    }

    const int row0 = bm + wm, col0 = bn + wn;
#pragma unroll
    for (int i = 0; i < 2; i++)
#pragma unroll
        for (int j = 0; j < 4; j++) {
            wmma::fragment<wmma::accumulator, 16, 16, 8, float> bfr;
            wmma::load_matrix_sync(bfr, bias_s + wn + j * 16, 128, wmma::mem_row_major);
#pragma unroll
            for (int e = 0; e < bfr.num_elements; e++)
                acc[i][j].x[e] += bfr.x[e];
            wmma::store_matrix_sync(g_xg + (size_t)(row0 + i * 16) * G4 + col0 + j * 16,
                                    acc[i][j], G4, wmma::mem_row_major);
        }
}

// ---------------- generic fp32 SGEMM (prenet + proj) ----------------
__device__ __forceinline__ int swz(int c) { return c + ((c >> 5) << 2); }

__global__ __launch_bounds__(256, 2)
void sgemm_kernel(const float* __restrict__ A1, int lda1,
                  const float* __restrict__ A2, int lda2, int split,
                  const float* __restrict__ W,
                  const float* __restrict__ bias, int relu, int rnd,
                  float* __restrict__ C, int N, int K)
{
    __shared__ float As[16][132];
    __shared__ float Bs[16][144];
    const int tid = threadIdx.x;
    const int tx = tid & 15, ty = tid >> 4;
    const int bm = blockIdx.y << 7, bn = blockIdx.x << 7;

    ull acc[8][4];
#pragma unroll
    for (int i = 0; i < 8; i++)
#pragma unroll
        for (int j = 0; j < 4; j++) acc[i][j] = 0ull;

    const int aq0 = tid, aq1 = tid + 256;
    const int ar0 = aq0 >> 2, ak0 = (aq0 & 3) << 2;
    const int ar1 = aq1 >> 2, ak1 = (aq1 & 3) << 2;
    const int bkk = tid >> 5, bcc = (tid & 31) << 2;

    float4 pa0, pa1, pb0, pb1;

    auto ldTiles = [&](int k0) {
        int kg0 = k0 + ak0;
        pa0 = (kg0 < split)
            ? *(const float4*)(A1 + (size_t)(bm + ar0) * lda1 + kg0)
            : *(const float4*)(A2 + (size_t)(bm + ar0) * lda2 + (kg0 - split));
        int kg1 = k0 + ak1;
        pa1 = (kg1 < split)
            ? *(const float4*)(A1 + (size_t)(bm + ar1) * lda1 + kg1)
            : *(const float4*)(A2 + (size_t)(bm + ar1) * lda2 + (kg1 - split));
        pb0 = *(const float4*)(W + (size_t)(k0 + bkk) * N + bn + bcc);
        pb1 = *(const float4*)(W + (size_t)(k0 + bkk + 8) * N + bn + bcc);
    };
    auto stTiles = [&]() {
        As[ak0 + 0][ar0] = pa0.x; As[ak0 + 1][ar0] = pa0.y;
        As[ak0 + 2][ar0] = pa0.z; As[ak0 + 3][ar0] = pa0.w;
        As[ak1 + 0][ar1] = pa1.x; As[ak1 + 1][ar1] = pa1.y;
        As[ak1 + 2][ar1] = pa1.z; As[ak1 + 3][ar1] = pa1.w;
        *(float4*)&Bs[bkk][swz(bcc)] = pb0;
        *(float4*)&Bs[bkk + 8][swz(bcc)] = pb1;
    };
    auto comp = [&]() {
#pragma unroll
        for (int kk = 0; kk < 16; kk++) {
            float4 a0 = *(const float4*)&As[kk][ty << 3];
            float4 a1 = *(const float4*)&As[kk][(ty << 3) + 4];
            ulonglong2 b01 = *(const ulonglong2*)&Bs[kk][swz(tx << 3)];
            ulonglong2 b23 = *(const ulonglong2*)&Bs[kk][swz((tx << 3) + 4)];
            float ar[8] = {a0.x, a0.y, a0.z, a0.w, a1.x, a1.y, a1.z, a1.w};
#pragma unroll
            for (int i = 0; i < 8; i++) {
                ull av = pk2(ar[i], ar[i]);
                fma2(acc[i][0], av, b01.x);
                fma2(acc[i][1], av, b01.y);
                fma2(acc[i][2], av, b23.x);
                fma2(acc[i][3], av, b23.y);
            }
        }
    };

    ldTiles(0);
    stTiles();
    __syncthreads();
    for (int k0 = 0; k0 < K; k0 += 16) {
        bool more = (k0 + 16) < K;
        if (more) ldTiles(k0 + 16);
        comp();
        __syncthreads();
        if (more) { stTiles(); __syncthreads(); }
    }

#pragma unroll
    for (int i = 0; i < 8; i++) {
        int row = bm + (ty << 3) + i;
        float* cp = C + (size_t)row * N + bn + (tx << 3);
#pragma unroll
        for (int j = 0; j < 4; j++) {
            float2 v = upk2(acc[i][j]);
            if (bias) {
                int col = bn + (tx << 3) + 2 * j;
                v.x += bias[col]; v.y += bias[col + 1];
            }
            if (relu) { v.x = fmaxf(v.x, 0.f); v.y = fmaxf(v.y, 0.f); }
            if (rnd)  { v.x = rtf32(v.x); v.y = rtf32(v.y); }
            *(float2*)(cp + 2 * j) = v;
        }
    }
}

// ---------------- tensor-core persistent LSTM scan (mma.sync m16n8k8 tf32) ----------------
// 128 blocks x 512 threads (16 warps). Block owns units [6k,6k+6) -> 24 gate cols
// padded to 32 (col=q*8+u, u<6). B = w_hh slice [768][36] tf32 in SMEM (resident).
// A fragments loaded per-thread via __ldcg from g_h [j][b] (L2-coherent, coalesced publish).
// Warp w: rhalf=w&1 (16 batch rows), k8=w>>1 (96 k = 12 chunks of 8).
#define PB_LD 36
#define SB_P  (768 * PB_LD)                 // after Bs
#define SB_C  (SB_P + 8 * 32 * PB_LD)       // after P
#define SCAN2_FLOATS (SB_C + 192)           // 37056 floats = 148224 B

__device__ __forceinline__ void pre_xg(int t, int tid, int j0, float* xgv) {
    if (tid < 192) {
        int u = tid >> 5, b = tid & 31;
        const float* xp = g_xg + (size_t)(b * T_ + t) * G4 + j0 + u;
        xgv[0] = __ldcg(xp);
        xgv[1] = __ldcg(xp + H_);
        xgv[2] = __ldcg(xp + 2 * H_);
        xgv[3] = __ldcg(xp + 3 * H_);
    }
}

__global__ __launch_bounds__(512, 1)
void scan_mma_kernel(const float* __restrict__ w_hh)
{
    extern __shared__ float sm[];
    float* Bs  = sm;                 // [768][36], cols 0..31 valid (24 real + zero pad)
    float* P   = sm + SB_P;          // [8 k-groups][32 rows][36]
    float* c_s = sm + SB_C;          // [192]

    const int tid = threadIdx.x, lane = tid & 31, warp = tid >> 5;
    const int j0 = blockIdx.x * 6;
    const int rhalf = warp & 1, k8 = warp >> 1;
    const int t4 = lane & 3, g = lane >> 2;
    const int row0 = rhalf * 16 + g;

    // B fill: col c = q*8+u (u<6 real, else 0), tf32-rounded
    for (int idx = tid; idx < 768 * 32; idx += 512) {
        int k = idx >> 5, c = idx & 31;
        int q = c >> 3, u = c & 7;
        float v = (u < 6) ? w_hh[(size_t)k * G4 + q * H_ + j0 + u] : 0.f;
        Bs[k * PB_LD + c] = rtf32(v);
    }
    if (tid < 192) {
        c_s[tid] = 0.f;
        int u = tid >> 5, b = tid & 31;
        g_h[0][(j0 + u) * 32 + b] = 0.f;
    }
    __syncthreads();
    if (tid == 0) {
        __threadfence();
        asm volatile("st.release.gpu.u32 [%0],%1;"
                     :: "l"(&g_flag[blockIdx.x << 5]), "r"(1u) : "memory");
    }

    // per-warp wait: this warp's 16 producer blocks (k-range k8*96 -> blocks 16*k8..+15)
    const unsigned* fpp = &g_flag[(k8 * 16 + (lane & 15)) << 5];

    float xga[4];
    pre_xg(0, tid, j0, xga);

    for (int t = 0; t < T_; t++) {
        const float* hcur = g_h[t & 1];
        float*       hnxt = g_h[(t + 1) & 1];
        const unsigned target = (unsigned)(t + 1);

        unsigned v;
        do {
            asm volatile("ld.acquire.gpu.u32 %0,[%1];" : "=r"(v) : "l"(fpp) : "memory");
        } while (!__all_sync(0xffffffffu, v >= target));

        float xgb[4];
        pre_xg(t + 1 < T_ ? t + 1 : T_ - 1, tid, j0, xgb);

        float acc[16];
#pragma unroll
        for (int i = 0; i < 16; i++) acc[i] = 0.f;

#pragma unroll
        for (int c = 0; c < 12; c++) {
            const int kb = k8 * 96 + c * 8;
            // A fragment direct from L2 (g_h layout [k][b])
            const float* ap = hcur + (size_t)(kb + t4) * 32 + row0;
            unsigned a0 = __float_as_uint(__ldcg(ap));
            unsigned a1 = __float_as_uint(__ldcg(ap + 8));
            unsigned a2 = __float_as_uint(__ldcg(ap + 4 * 32));
            unsigned a3 = __float_as_uint(__ldcg(ap + 4 * 32 + 8));
            const float* bp = Bs + (size_t)(kb + t4) * PB_LD + g;
#pragma unroll
            for (int nb = 0; nb < 4; nb++) {
                unsigned b0 = __float_as_uint(bp[nb * 8]);
                unsigned b1 = __float_as_uint(bp[4 * PB_LD + nb * 8]);
                mma8(acc[nb * 4 + 0], acc[nb * 4 + 1], acc[nb * 4 + 2], acc[nb * 4 + 3],
                     a0, a1, a2, a3, b0, b1);
            }
        }

        // store partials: P[k8][row][col]
        {
            float* pp = P + k8 * (32 * PB_LD);
#pragma unroll
            for (int nb = 0; nb < 4; nb++) {
                int col = nb * 8 + 2 * t4;
                pp[row0 * PB_LD + col]           = acc[nb * 4 + 0];
                pp[row0 * PB_LD + col + 1]       = acc[nb * 4 + 1];
                pp[(row0 + 8) * PB_LD + col]     = acc[nb * 4 + 2];
                pp[(row0 + 8) * PB_LD + col + 1] = acc[nb * 4 + 3];
            }
        }
        __syncthreads();

        // gates: thread (u,b); 8-way partial add
        float hn = 0.f;
        if (tid < 192) {
            int u = tid >> 5, b = tid & 31;
            float pre[4];
#pragma unroll
            for (int q = 0; q < 4; q++) {
                int off = b * PB_LD + q * 8 + u;
                float s0 = P[off]                  + P[1 * 32 * PB_LD + off];
                float s1 = P[2 * 32 * PB_LD + off] + P[3 * 32 * PB_LD + off];
                float s2 = P[4 * 32 * PB_LD + off] + P[5 * 32 * PB_LD + off];
                float s3 = P[6 * 32 * PB_LD + off] + P[7 * 32 * PB_LD + off];
                pre[q] = xga[q] + ((s0 + s1) + (s2 + s3));
            }
            float ig = sigf(pre[0]);
            float fg = sigf(pre[1]);
            float gg = tanh_(pre[2]);
            float og = sigf(pre[3]);
            float cn = fg * c_s[u * 32 + b] + ig * gg;
            c_s[u * 32 + b] = cn;
            hn = og * tanh_(cn);
            hnxt[(j0 + u) * 32 + b] = rtf32(hn);   // coalesced tf32 publish (MMA A input)
        }
        __syncthreads();
        if (tid == 0) {
            __threadfence();
            asm volatile("st.release.gpu.u32 [%0],%1;"
                         :: "l"(&g_flag[blockIdx.x << 5]), "r"((unsigned)(t + 2)) : "memory");
        }

        // off-critical-path fp32 h for the projection
        if (tid < 192) {
            int u = tid >> 5, b = tid & 31;
            g_hs[(size_t)(b * T_ + t) * H_ + j0 + u] = hn;
        }

        xga[0] = xgb[0]; xga[1] = xgb[1]; xga[2] = xgb[2]; xga[3] = xgb[3];
    }
}

// ---------------- host launcher ----------------
extern "C" void kernel_launch(void* const* d_in, const int* in_sizes, int n_in,
                              void* d_out, int out_size)
{
    const float* x      = (const float*)d_in[0];
    const float* mels   = (const float*)d_in[1];
    const float* w1     = (const float*)d_in[2];
    const float* b1     = (const float*)d_in[3];
    const float* w2     = (const float*)d_in[4];
    const float* b2     = (const float*)d_in[5];
    const float* w_ih   = (const float*)d_in[6];
    const float* w_hh   = (const float*)d_in[7];
    const float* b_ih   = (const float*)d_in[8];
    const float* b_hh   = (const float*)d_in[9];
    const float* w_proj = (const float*)d_in[10];
    float* out = (float*)d_out;

    float *p_m1, *p_m2, *p_hs;
    cudaGetSymbolAddress((void**)&p_m1, g_m1);
    cudaGetSymbolAddress((void**)&p_m2, g_m2);
    cudaGetSymbolAddress((void**)&p_hs, g_hs);

    cudaFuncSetAttribute(scan_mma_kernel, cudaFuncAttributeMaxDynamicSharedMemorySize,
                         SCAN2_FLOATS * 4);
    cudaFuncSetAttribute(xg_wmma_kernel, cudaFuncAttributeMaxDynamicSharedMemorySize,
                         XS_TOTAL * 4);

    // init + tf32 pre-rounding
    init_kernel<<<16, 256>>>(b_ih, b_hh);
    round_x_kernel<<<BT * 512 / 1024, 256>>>(x);
    round_w_kernel<<<H_ * G4 / 1024, 256>>>(w_ih);

    // PreNet layer 1: [65536,128] @ [128,256] + b1, relu
    sgemm_kernel<<<dim3(2, 512), 256>>>(mels, 128, mels, 128, 128,
                                        w1, b1, 1, 0, p_m1, 256, 128);
    // PreNet layer 2: + b2, relu, output rounded to tf32 (feeds xg tensor GEMM)
    sgemm_kernel<<<dim3(2, 512), 256>>>(p_m1, 256, p_m1, 256, 256,
                                        w2, b2, 1, 1, p_m2, 256, 256);

    // xg = concat(xr, m2) @ wr + bias  — tf32 mma.sync (R9 exact)
    xg_wmma_kernel<<<dim3(24, 512), 256, XS_TOTAL * 4>>>(p_m2);

    // LSTM recurrence — tensor-core persistent scan (mma.sync)
    scan_mma_kernel<<<128, 512, SCAN2_FLOATS * 4>>>(w_hh);

    // projection: [65536,768] @ [768,128] — fp32 (R9 exact)
    sgemm_kernel<<<dim3(1, 512), 256>>>(p_hs, 768, p_hs, 768, 768,
                                        w_proj, nullptr, 0, 0, out, 128, 768);
}